// round 2
// baseline (speedup 1.0000x reference)
#include <cuda_runtime.h>

#define B_    4
#define CDIM  96
#define L_    9216
#define DM    192
#define NS    16
#define RT    6
#define BL    (B_*L_)
#define TT    128
#define NTILE (BL/TT)     /* 288 */
#define G_    96
#define NCH   (L_/G_)     /* 96 */

/* ---- scratch (device globals: allocation-free) ---- */
__device__ float g_xin[(size_t)B_*DM*L_];   // in_proj out,   [b][d][l]
__device__ float g_xc [(size_t)B_*DM*L_];   // conv+silu out, [b][d][l]
__device__ float g_kp [(size_t)B_*DM*L_];   // K path,        [b][d][l]
__device__ float g_qp [(size_t)B_*DM*L_];   // Q path,        [b][d][l]
__device__ float g_dl [(size_t)B_*DM*L_];   // delta,         [b][d][l]
__device__ float g_z  [(size_t)B_*DM*L_];   // gate pre-silu, [b][d][l]
__device__ float g_Bs [(size_t)B_*NS*L_];   // B,             [b][n][l]
__device__ float g_Cs [(size_t)B_*NS*L_];   // C,             [b][n][l]
__device__ float g_y  [(size_t)BL*DM];      // gated scan out, token-major [tok][d]
__device__ float g_P  [(size_t)B_*NCH*DM*NS];
__device__ float g_Hl [(size_t)B_*NCH*DM*NS];
__device__ float g_Hi [(size_t)B_*NCH*DM*NS];

__device__ __forceinline__ float siluf(float v) { return v / (1.0f + __expf(-v)); }

/* ============ GEMM config A: K=96, N=192, optional LN + bias + silu ============
   src: [b][96][L] channel-major. dst: g_xin / g_kp / g_qp (selector).
   512 threads, 128-token tile; thread = 4 tokens x 12 outs. */
__global__ void __launch_bounds__(512)
gemm_ln_k96(const float* __restrict__ src, const float* __restrict__ W,
            const float* __restrict__ bias, const float* __restrict__ lng,
            const float* __restrict__ lnb, int dstSel, int doLN, int actSilu)
{
    extern __shared__ float sm[];
    float* xs = sm;                      // 96*129
    float* ws = sm + 96*129;             // 192*96
    float* mean_s = ws + 192*96;         // 128
    float* rstd_s = mean_s + 128;        // 128
    int tid = threadIdx.x;
    int tok0 = blockIdx.x * TT;
    int b = tok0 / L_, l0 = tok0 % L_;
    const float* srcb = src + ((size_t)b*CDIM)*L_ + l0;

    for (int i = tid; i < DM*CDIM; i += 512) ws[i] = W[i];
    for (int i = tid; i < CDIM*TT; i += 512) {
        int t = i % TT, k = i / TT;
        xs[k*129 + t] = srcb[(size_t)k*L_ + t];
    }
    __syncthreads();

    if (doLN) {
        if (tid < TT) {
            float s = 0.f, ss = 0.f;
            for (int c = 0; c < CDIM; c++) { float v = xs[c*129 + tid]; s += v; ss += v*v; }
            float m = s * (1.0f/CDIM);
            float var = ss * (1.0f/CDIM) - m*m;
            mean_s[tid] = m;
            rstd_s[tid] = rsqrtf(var + 1e-5f);
        }
        __syncthreads();
        for (int i = tid; i < CDIM*TT; i += 512) {
            int t = i % TT, c = i / TT;
            xs[c*129 + t] = (xs[c*129 + t] - mean_s[t]) * rstd_s[t] * lng[c] + lnb[c];
        }
        __syncthreads();
    }

    int tx = tid & 31, ty = tid >> 5;    // ty: 0..15
    float acc[4][12];
    #pragma unroll
    for (int m = 0; m < 4; m++)
        #pragma unroll
        for (int j = 0; j < 12; j++) acc[m][j] = 0.f;

    for (int k = 0; k < CDIM; k++) {
        float xv[4];
        #pragma unroll
        for (int m = 0; m < 4; m++) xv[m] = xs[k*129 + tx + 32*m];
        #pragma unroll
        for (int j = 0; j < 12; j++) {
            float wv = ws[(ty + 16*j)*CDIM + k];
            #pragma unroll
            for (int m = 0; m < 4; m++) acc[m][j] = fmaf(wv, xv[m], acc[m][j]);
        }
    }

    float* dst = (dstSel == 0) ? g_xin : ((dstSel == 1) ? g_kp : g_qp);
    float* dstb = dst + ((size_t)b*DM)*L_ + l0;
    #pragma unroll
    for (int j = 0; j < 12; j++) {
        int c = ty + 16*j;
        float bv = bias ? bias[c] : 0.f;
        #pragma unroll
        for (int m = 0; m < 4; m++) {
            float v = acc[m][j] + bv;
            if (actSilu) v = siluf(v);
            dstb[(size_t)c*L_ + tx + 32*m] = v;
        }
    }
}

/* ============ depthwise causal conv (k=4) + silu: g_xin -> g_xc ============ */
__global__ void __launch_bounds__(256)
conv_silu(const float* __restrict__ cw, const float* __restrict__ cb)
{
    int gid = blockIdx.x * blockDim.x + threadIdx.x;   // over B*DM*L, l fastest
    if (gid >= B_*DM*L_) return;
    int l  = gid % L_;
    int bd = gid / L_;
    int d  = bd % DM;
    const float* p = g_xin + (size_t)bd*L_ + l;
    float acc = cb[d] + cw[d*4+3] * p[0];
    if (l >= 1) acc = fmaf(cw[d*4+2], p[-1], acc);
    if (l >= 2) acc = fmaf(cw[d*4+1], p[-2], acc);
    if (l >= 3) acc = fmaf(cw[d*4+0], p[-3], acc);
    g_xc[gid] = siluf(acc);
}

/* ============ dtbc: x_dbl = cat(xc,kp) @ dtbc_w^T, then delta/B/C ============ */
__global__ void __launch_bounds__(512)
dtbc_kernel(const float* __restrict__ dtbc_w, const float* __restrict__ dt_w,
            const float* __restrict__ dt_b)
{
    extern __shared__ float sm[];
    float* xs   = sm;                    // 96*129
    float* ws   = xs + 96*129;           // 38*96
    float* dbl  = ws + 38*96;            // 38*129
    float* dtw  = dbl + 38*129;          // 192*6
    float* dtb  = dtw + 192*6;           // 192
    int tid = threadIdx.x;
    int tok0 = blockIdx.x * TT;
    int b = tok0 / L_, l0 = tok0 % L_;

    for (int i = tid; i < DM*RT; i += 512) dtw[i] = dt_w[i];
    for (int i = tid; i < DM;    i += 512) dtb[i] = dt_b[i];

    int tx = tid & 31, ty = tid >> 5;    // ty: 0..15
    float acc[4][3];
    #pragma unroll
    for (int m = 0; m < 4; m++)
        #pragma unroll
        for (int j = 0; j < 3; j++) acc[m][j] = 0.f;

    for (int kc = 0; kc < 4; kc++) {
        const float* src = (kc < 2) ? g_xc : g_kp;
        int k0 = (kc & 1) * 96;
        __syncthreads();
        for (int i = tid; i < 96*TT; i += 512) {
            int t = i % TT, k = i / TT;
            xs[k*129 + t] = src[((size_t)b*DM + k0 + k)*L_ + l0 + t];
        }
        for (int i = tid; i < 38*96; i += 512) {
            int c = i / 96, kk = i % 96;
            ws[i] = dtbc_w[c*384 + kc*96 + kk];
        }
        __syncthreads();
        for (int k = 0; k < 96; k++) {
            float xv[4];
            #pragma unroll
            for (int m = 0; m < 4; m++) xv[m] = xs[k*129 + tx + 32*m];
            #pragma unroll
            for (int j = 0; j < 3; j++) {
                int c = ty + 16*j;
                if (c < 38) {
                    float wv = ws[c*96 + k];
                    #pragma unroll
                    for (int m = 0; m < 4; m++) acc[m][j] = fmaf(wv, xv[m], acc[m][j]);
                }
            }
        }
    }
    __syncthreads();
    #pragma unroll
    for (int j = 0; j < 3; j++) {
        int c = ty + 16*j;
        if (c < 38)
            #pragma unroll
            for (int m = 0; m < 4; m++) dbl[c*129 + tx + 32*m] = acc[m][j];
    }
    __syncthreads();

    /* delta = softplus(dt @ dt_w^T + 2*dt_b), channel-major write */
    for (int i = tid; i < DM*TT; i += 512) {
        int t = i % TT, d = i / TT;
        float s = 2.0f * dtb[d];
        #pragma unroll
        for (int r = 0; r < RT; r++) s = fmaf(dbl[r*129 + t], dtw[d*RT + r], s);
        float dl = (s > 20.f) ? s : log1pf(__expf(s));
        g_dl[((size_t)b*DM + d)*L_ + l0 + t] = dl;
    }
    /* B, C channel-major */
    for (int i = tid; i < 2*NS*TT; i += 512) {
        int t = i % TT, q = i / TT;
        float v = dbl[(RT + q)*129 + t];
        if (q < NS) g_Bs[((size_t)b*NS + q)*L_ + l0 + t] = v;
        else        g_Cs[((size_t)b*NS + (q-NS))*L_ + l0 + t] = v;
    }
}

/* ============ gate: z = cat(xc,qp) @ gate_w^T + gate_b ============ */
__global__ void __launch_bounds__(512)
gate_kernel(const float* __restrict__ gate_w, const float* __restrict__ gate_b)
{
    extern __shared__ float sm[];
    float* xs = sm;              // 96*129
    float* ws = xs + 96*129;     // 192*96
    int tid = threadIdx.x;
    int tok0 = blockIdx.x * TT;
    int b = tok0 / L_, l0 = tok0 % L_;
    int tx = tid & 31, ty = tid >> 5;

    float acc[4][12];
    #pragma unroll
    for (int m = 0; m < 4; m++)
        #pragma unroll
        for (int j = 0; j < 12; j++) acc[m][j] = 0.f;

    for (int kc = 0; kc < 4; kc++) {
        const float* src = (kc < 2) ? g_xc : g_qp;
        int k0 = (kc & 1) * 96;
        __syncthreads();
        for (int i = tid; i < 96*TT; i += 512) {
            int t = i % TT, k = i / TT;
            xs[k*129 + t] = src[((size_t)b*DM + k0 + k)*L_ + l0 + t];
        }
        for (int i = tid; i < DM*96; i += 512) {
            int c = i / 96, kk = i % 96;
            ws[i] = gate_w[c*384 + kc*96 + kk];
        }
        __syncthreads();
        for (int k = 0; k < 96; k++) {
            float xv[4];
            #pragma unroll
            for (int m = 0; m < 4; m++) xv[m] = xs[k*129 + tx + 32*m];
            #pragma unroll
            for (int j = 0; j < 12; j++) {
                float wv = ws[(ty + 16*j)*96 + k];
                #pragma unroll
                for (int m = 0; m < 4; m++) acc[m][j] = fmaf(wv, xv[m], acc[m][j]);
            }
        }
    }
    float* dstb = g_z + ((size_t)b*DM)*L_ + l0;
    #pragma unroll
    for (int j = 0; j < 12; j++) {
        int c = ty + 16*j;
        float bv = gate_b[c];
        #pragma unroll
        for (int m = 0; m < 4; m++)
            dstb[(size_t)c*L_ + tx + 32*m] = acc[m][j] + bv;
    }
}

/* ============ chunked selective scan ============ */
/* pass 1: per-chunk local scan from h=0; store decay product P and local end-state */
__global__ void __launch_bounds__(256)
scan1(const float* __restrict__ A_log)
{
    int b = blockIdx.z, ch = blockIdx.y, dblk = blockIdx.x;
    int tid = threadIdx.x;
    int w = tid >> 5, lane = tid & 31;
    int n = lane & 15, dsub = lane >> 4;
    int d = dblk*16 + w*2 + dsub;
    float A = -__expf(A_log[d*NS + n]);
    const float* dp = g_dl + ((size_t)b*DM + d)*L_ + ch*G_;
    const float* up = g_xc + ((size_t)b*DM + d)*L_ + ch*G_;
    const float* bp = g_Bs + ((size_t)b*NS + n)*L_ + ch*G_;
    float h = 0.f, P = 1.f;
    #pragma unroll 4
    for (int t = 0; t < G_; t++) {
        float dl = dp[t];
        float a = __expf(dl * A);
        P *= a;
        h = fmaf(a, h, dl * up[t] * bp[t]);
    }
    size_t o = (((size_t)(b*NCH + ch))*DM + d)*NS + n;
    g_P[o] = P; g_Hl[o] = h;
}

/* pass 2: combine chunk states sequentially (96 steps over 12288 lanes) */
__global__ void __launch_bounds__(256)
scan2()
{
    int idx = blockIdx.x * blockDim.x + threadIdx.x;
    if (idx >= B_*DM*NS) return;
    int b = idx / (DM*NS);
    int dn = idx % (DM*NS);
    float h = 0.f;
    for (int ch = 0; ch < NCH; ch++) {
        size_t o = ((size_t)(b*NCH + ch))*(DM*NS) + dn;
        g_Hi[o] = h;
        h = fmaf(g_P[o], h, g_Hl[o]);
    }
}

/* pass 3: re-scan with correct h0, reduce over n, add D-skip, gate with silu(z) */
__global__ void __launch_bounds__(256)
scan3(const float* __restrict__ A_log, const float* __restrict__ Dp)
{
    int b = blockIdx.z, ch = blockIdx.y, dblk = blockIdx.x;
    int tid = threadIdx.x;
    int w = tid >> 5, lane = tid & 31;
    int n = lane & 15, dsub = lane >> 4;
    int d = dblk*16 + w*2 + dsub;
    float A = -__expf(A_log[d*NS + n]);
    const float* dp = g_dl + ((size_t)b*DM + d)*L_ + ch*G_;
    const float* up = g_xc + ((size_t)b*DM + d)*L_ + ch*G_;
    const float* zp = g_z  + ((size_t)b*DM + d)*L_ + ch*G_;
    const float* bp = g_Bs + ((size_t)b*NS + n)*L_ + ch*G_;
    const float* cp = g_Cs + ((size_t)b*NS + n)*L_ + ch*G_;
    size_t o = (((size_t)(b*NCH + ch))*DM + d)*NS + n;
    float h = g_Hi[o];
    float Dd = Dp[d];
    for (int t = 0; t < G_; t++) {
        float dl = dp[t];
        float u  = up[t];
        float a = __expf(dl * A);
        h = fmaf(a, h, dl * u * bp[t]);
        float v = h * cp[t];
        v += __shfl_xor_sync(0xffffffffu, v, 1);
        v += __shfl_xor_sync(0xffffffffu, v, 2);
        v += __shfl_xor_sync(0xffffffffu, v, 4);
        v += __shfl_xor_sync(0xffffffffu, v, 8);
        if (n == 0) {
            float zt = zp[t];
            float yy = (v + u * Dd) * siluf(zt);
            g_y[((size_t)(b*L_ + ch*G_ + t))*DM + d] = yy;
        }
    }
}

/* ============ out projection: out[b][c][l] = y[tok][:] @ out_w[c][:] ============ */
__global__ void __launch_bounds__(512)
gemm_out(const float* __restrict__ out_w, float* __restrict__ out)
{
    extern __shared__ float sm[];
    float* xs = sm;              // 96*129
    float* ws = xs + 96*129;     // 96*192
    int tid = threadIdx.x;
    int tok0 = blockIdx.x * TT;
    int b = tok0 / L_, l0 = tok0 % L_;
    for (int i = tid; i < CDIM*DM; i += 512) ws[i] = out_w[i];
    int tx = tid & 31, ty = tid >> 5;
    float acc[4][6];
    #pragma unroll
    for (int m = 0; m < 4; m++)
        #pragma unroll
        for (int j = 0; j < 6; j++) acc[m][j] = 0.f;

    for (int kc = 0; kc < 2; kc++) {
        __syncthreads();
        for (int i = tid; i < 96*TT; i += 512) {
            int k = i % 96, t = i / 96;
            xs[k*129 + t] = g_y[((size_t)tok0 + t)*DM + kc*96 + k];
        }
        __syncthreads();
        for (int k = 0; k < 96; k++) {
            float xv[4];
            #pragma unroll
            for (int m = 0; m < 4; m++) xv[m] = xs[k*129 + tx + 32*m];
            #pragma unroll
            for (int j = 0; j < 6; j++) {
                float wv = ws[(ty + 16*j)*DM + kc*96 + k];
                #pragma unroll
                for (int m = 0; m < 4; m++) acc[m][j] = fmaf(wv, xv[m], acc[m][j]);
            }
        }
    }
    float* ob = out + ((size_t)b*CDIM)*L_ + l0;
    #pragma unroll
    for (int j = 0; j < 6; j++) {
        int c = ty + 16*j;
        #pragma unroll
        for (int m = 0; m < 4; m++)
            ob[(size_t)c*L_ + tx + 32*m] = acc[m][j];
    }
}

/* ============ host launcher ============ */
extern "C" void kernel_launch(void* const* d_in, const int* in_sizes, int n_in,
                              void* d_out, int out_size)
{
    const float* x         = (const float*)d_in[0];
    const float* Kin       = (const float*)d_in[1];
    const float* Qin       = (const float*)d_in[2];
    const float* in_proj_w = (const float*)d_in[3];
    const float* conv_w    = (const float*)d_in[4];
    const float* conv_b    = (const float*)d_in[5];
    const float* k_ln_g    = (const float*)d_in[6];
    const float* k_ln_b    = (const float*)d_in[7];
    const float* k_w       = (const float*)d_in[8];
    const float* k_b       = (const float*)d_in[9];
    const float* q_ln_g    = (const float*)d_in[10];
    const float* q_ln_b    = (const float*)d_in[11];
    const float* q_w       = (const float*)d_in[12];
    const float* q_b       = (const float*)d_in[13];
    const float* dtbc_w    = (const float*)d_in[14];
    const float* dt_w      = (const float*)d_in[15];
    const float* dt_b      = (const float*)d_in[16];
    const float* gate_w    = (const float*)d_in[17];
    const float* gate_b    = (const float*)d_in[18];
    const float* A_log     = (const float*)d_in[19];
    const float* Dp        = (const float*)d_in[20];
    const float* out_w     = (const float*)d_in[21];
    float* out = (float*)d_out;

    const int SMEM_A = (96*129 + 192*96 + 256) * 4;          /* 124 KB */
    const int SMEM_G = (96*129 + 192*96) * 4;                /* 123 KB */
    const int SMEM_D = (96*129 + 38*96 + 38*129 + 192*6 + 192) * 4;  /* ~87 KB */
    const int SMEM_O = (96*129 + 96*192) * 4;                /* 120 KB */

    cudaFuncSetAttribute(gemm_ln_k96, cudaFuncAttributeMaxDynamicSharedMemorySize, SMEM_A);
    cudaFuncSetAttribute(gate_kernel, cudaFuncAttributeMaxDynamicSharedMemorySize, SMEM_G);
    cudaFuncSetAttribute(dtbc_kernel, cudaFuncAttributeMaxDynamicSharedMemorySize, SMEM_D);
    cudaFuncSetAttribute(gemm_out,    cudaFuncAttributeMaxDynamicSharedMemorySize, SMEM_O);

    /* 1. in_proj (no LN, no act) -> g_xin */
    gemm_ln_k96<<<NTILE, 512, SMEM_A>>>(x, in_proj_w, nullptr, nullptr, nullptr, 0, 0, 0);
    /* 2. depthwise conv + silu -> g_xc */
    conv_silu<<<(B_*DM*L_)/256, 256>>>(conv_w, conv_b);
    /* 3. K and Q paths (LN + proj + bias + silu) */
    gemm_ln_k96<<<NTILE, 512, SMEM_A>>>(Kin, k_w, k_b, k_ln_g, k_ln_b, 1, 1, 1);
    gemm_ln_k96<<<NTILE, 512, SMEM_A>>>(Qin, q_w, q_b, q_ln_g, q_ln_b, 2, 1, 1);
    /* 4. dtbc -> delta, B, C */
    dtbc_kernel<<<NTILE, 512, SMEM_D>>>(dtbc_w, dt_w, dt_b);
    /* 5. gate -> z */
    gate_kernel<<<NTILE, 512, SMEM_G>>>(gate_w, gate_b);
    /* 6-8. chunked selective scan */
    scan1<<<dim3(DM/16, NCH, B_), 256>>>(A_log);
    scan2<<<(B_*DM*NS)/256, 256>>>();
    scan3<<<dim3(DM/16, NCH, B_), 256>>>(A_log, Dp);
    /* 9. output projection (writes transposed layout directly) */
    gemm_out<<<NTILE, 512, SMEM_O>>>(out_w, out);
}

// round 7
// speedup vs baseline: 3.0994x; 3.0994x over previous
#include <cuda_runtime.h>

#define B_    4
#define CDIM  96
#define L_    9216
#define DM    192
#define NS    16
#define RT    6
#define BL    (B_*L_)
#define TT    128
#define NTILE (BL/TT)     /* 288 */
#define G_    96
#define NCH   (L_/G_)     /* 96 */
#define TTP   132         /* padded token row for xs (16B aligned, bank-shifted) */

/* ---- scratch (device globals: allocation-free) ---- */
__device__ float g_xin[(size_t)B_*DM*L_];   // in_proj out,   [b][d][l]
__device__ float g_xc [(size_t)B_*DM*L_];   // conv+silu out, [b][d][l]
__device__ float g_kp [(size_t)B_*DM*L_];   // K path,        [b][d][l]
__device__ float g_qp [(size_t)B_*DM*L_];   // Q path,        [b][d][l]
__device__ float g_dl [(size_t)B_*DM*L_];   // delta,         [b][d][l]
__device__ float g_z  [(size_t)B_*DM*L_];   // silu(gate),    [b][d][l]
__device__ float g_Bs [(size_t)B_*NS*L_];   // B,             [b][n][l]
__device__ float g_Cs [(size_t)B_*NS*L_];   // C,             [b][n][l]
__device__ float g_y  [(size_t)B_*DM*L_];   // gated scan out,[b][d][l]
__device__ float g_P  [(size_t)B_*NCH*DM*NS];
__device__ float g_Hl [(size_t)B_*NCH*DM*NS];
__device__ float g_Hi [(size_t)B_*NCH*DM*NS];

__device__ __forceinline__ float siluf(float v) { return v / (1.0f + __expf(-v)); }

/* ============ fused 3x GEMM (in_proj / K-path / Q-path), K=96, N=192 ============
   blockIdx.y selects path. 512 thr; thread = 4 contiguous tokens x 12 outs.
   k-unroll 4 with float4 smem loads. */
__global__ void __launch_bounds__(512)
gemm3_k96(const float* __restrict__ x, const float* __restrict__ Kin,
          const float* __restrict__ Qin, const float* __restrict__ in_w,
          const float* __restrict__ k_w, const float* __restrict__ k_b,
          const float* __restrict__ k_ln_g, const float* __restrict__ k_ln_b,
          const float* __restrict__ q_w, const float* __restrict__ q_b,
          const float* __restrict__ q_ln_g, const float* __restrict__ q_ln_b)
{
    extern __shared__ float sm[];
    float* xs = sm;                      // 96*TTP
    float* ws = sm + 96*TTP;             // 192*96
    float* mean_s = ws + 192*96;         // 128
    float* rstd_s = mean_s + 128;        // 128

    int sel = blockIdx.y;
    const float* src  = (sel==0) ? x    : (sel==1 ? Kin    : Qin);
    const float* W    = (sel==0) ? in_w : (sel==1 ? k_w    : q_w);
    const float* bias = (sel==0) ? 0    : (sel==1 ? k_b    : q_b);
    const float* lng  = (sel==1) ? k_ln_g : q_ln_g;
    const float* lnb  = (sel==1) ? k_ln_b : q_ln_b;

    int tid = threadIdx.x;
    int tok0 = blockIdx.x * TT;
    int b = tok0 / L_, l0 = tok0 % L_;
    const float* srcb = src + ((size_t)b*CDIM)*L_ + l0;

    for (int i = tid; i < DM*CDIM; i += 512) ws[i] = W[i];
    for (int i = tid; i < CDIM*TT; i += 512) {
        int t = i % TT, k = i / TT;
        xs[k*TTP + t] = srcb[(size_t)k*L_ + t];
    }
    __syncthreads();

    if (sel != 0) {
        if (tid < TT) {
            float s = 0.f, ss = 0.f;
            for (int c = 0; c < CDIM; c++) { float v = xs[c*TTP + tid]; s += v; ss += v*v; }
            float m = s * (1.0f/CDIM);
            float var = ss * (1.0f/CDIM) - m*m;
            mean_s[tid] = m; rstd_s[tid] = rsqrtf(var + 1e-5f);
        }
        __syncthreads();
        for (int i = tid; i < CDIM*TT; i += 512) {
            int t = i % TT, c = i / TT;
            xs[c*TTP + t] = (xs[c*TTP + t] - mean_s[t]) * rstd_s[t] * lng[c] + lnb[c];
        }
        __syncthreads();
    }

    int tx = tid & 31, ty = tid >> 5;    // tokens tx*4..tx*4+3, outs ty+16j
    float acc[4][12];
    #pragma unroll
    for (int m = 0; m < 4; m++)
        #pragma unroll
        for (int j = 0; j < 12; j++) acc[m][j] = 0.f;

    #pragma unroll 2
    for (int kk = 0; kk < CDIM; kk += 4) {
        float4 xq[4];
        #pragma unroll
        for (int q = 0; q < 4; q++)
            xq[q] = *(const float4*)&xs[(kk+q)*TTP + tx*4];
        #pragma unroll
        for (int j = 0; j < 12; j++) {
            float4 wq = *(const float4*)&ws[(ty + 16*j)*CDIM + kk];
            acc[0][j] = fmaf(wq.x, xq[0].x, acc[0][j]);
            acc[1][j] = fmaf(wq.x, xq[0].y, acc[1][j]);
            acc[2][j] = fmaf(wq.x, xq[0].z, acc[2][j]);
            acc[3][j] = fmaf(wq.x, xq[0].w, acc[3][j]);
            acc[0][j] = fmaf(wq.y, xq[1].x, acc[0][j]);
            acc[1][j] = fmaf(wq.y, xq[1].y, acc[1][j]);
            acc[2][j] = fmaf(wq.y, xq[1].z, acc[2][j]);
            acc[3][j] = fmaf(wq.y, xq[1].w, acc[3][j]);
            acc[0][j] = fmaf(wq.z, xq[2].x, acc[0][j]);
            acc[1][j] = fmaf(wq.z, xq[2].y, acc[1][j]);
            acc[2][j] = fmaf(wq.z, xq[2].z, acc[2][j]);
            acc[3][j] = fmaf(wq.z, xq[2].w, acc[3][j]);
            acc[0][j] = fmaf(wq.w, xq[3].x, acc[0][j]);
            acc[1][j] = fmaf(wq.w, xq[3].y, acc[1][j]);
            acc[2][j] = fmaf(wq.w, xq[3].z, acc[2][j]);
            acc[3][j] = fmaf(wq.w, xq[3].w, acc[3][j]);
        }
    }

    float* dst = (sel == 0) ? g_xin : ((sel == 1) ? g_kp : g_qp);
    float* dstb = dst + ((size_t)b*DM)*L_ + l0;
    #pragma unroll
    for (int j = 0; j < 12; j++) {
        int c = ty + 16*j;
        float bv = bias ? bias[c] : 0.f;
        float4 v;
        v.x = acc[0][j] + bv; v.y = acc[1][j] + bv;
        v.z = acc[2][j] + bv; v.w = acc[3][j] + bv;
        if (sel != 0) { v.x = siluf(v.x); v.y = siluf(v.y); v.z = siluf(v.z); v.w = siluf(v.w); }
        *(float4*)&dstb[(size_t)c*L_ + tx*4] = v;
    }
}

/* ============ depthwise causal conv (k=4) + silu: g_xin -> g_xc ============ */
__global__ void __launch_bounds__(256)
conv_silu(const float* __restrict__ cw, const float* __restrict__ cb)
{
    int gid = blockIdx.x * blockDim.x + threadIdx.x;
    if (gid >= B_*DM*L_) return;
    int l  = gid % L_;
    int bd = gid / L_;
    int d  = bd % DM;
    const float* p = g_xin + (size_t)bd*L_ + l;
    float acc = cb[d] + cw[d*4+3] * p[0];
    if (l >= 1) acc = fmaf(cw[d*4+2], p[-1], acc);
    if (l >= 2) acc = fmaf(cw[d*4+1], p[-2], acc);
    if (l >= 3) acc = fmaf(cw[d*4+0], p[-3], acc);
    g_xc[gid] = siluf(acc);
}

/* ============ dtbc: x_dbl = cat(xc,kp) @ dtbc_w^T, then delta/B/C ============ */
__global__ void __launch_bounds__(512)
dtbc_kernel(const float* __restrict__ dtbc_w, const float* __restrict__ dt_w,
            const float* __restrict__ dt_b)
{
    extern __shared__ float sm[];
    float* xs   = sm;                    // 96*TTP
    float* ws   = xs + 96*TTP;           // 38*96
    float* dbl  = ws + 38*96;            // 38*TTP
    float* dtw  = dbl + 38*TTP;          // 192*6
    float* dtb  = dtw + 192*6;           // 192
    int tid = threadIdx.x;
    int tok0 = blockIdx.x * TT;
    int b = tok0 / L_, l0 = tok0 % L_;

    for (int i = tid; i < DM*RT; i += 512) dtw[i] = dt_w[i];
    for (int i = tid; i < DM;    i += 512) dtb[i] = dt_b[i];

    int tx = tid & 31, ty = tid >> 5;
    float acc[4][3];
    #pragma unroll
    for (int m = 0; m < 4; m++)
        #pragma unroll
        for (int j = 0; j < 3; j++) acc[m][j] = 0.f;

    for (int kc = 0; kc < 4; kc++) {
        const float* src = (kc < 2) ? g_xc : g_kp;
        int k0 = (kc & 1) * 96;
        __syncthreads();
        for (int i = tid; i < 96*TT; i += 512) {
            int t = i % TT, k = i / TT;
            xs[k*TTP + t] = src[((size_t)b*DM + k0 + k)*L_ + l0 + t];
        }
        for (int i = tid; i < 38*96; i += 512) {
            int c = i / 96, kk = i % 96;
            ws[i] = dtbc_w[c*384 + kc*96 + kk];
        }
        __syncthreads();
        #pragma unroll 2
        for (int kk = 0; kk < 96; kk += 4) {
            float4 xq[4];
            #pragma unroll
            for (int q = 0; q < 4; q++)
                xq[q] = *(const float4*)&xs[(kk+q)*TTP + tx*4];
            #pragma unroll
            for (int j = 0; j < 3; j++) {
                int c = ty + 16*j;
                if (c < 38) {
                    float4 wq = *(const float4*)&ws[c*96 + kk];
                    acc[0][j] = fmaf(wq.x, xq[0].x, acc[0][j]);
                    acc[1][j] = fmaf(wq.x, xq[0].y, acc[1][j]);
                    acc[2][j] = fmaf(wq.x, xq[0].z, acc[2][j]);
                    acc[3][j] = fmaf(wq.x, xq[0].w, acc[3][j]);
                    acc[0][j] = fmaf(wq.y, xq[1].x, acc[0][j]);
                    acc[1][j] = fmaf(wq.y, xq[1].y, acc[1][j]);
                    acc[2][j] = fmaf(wq.y, xq[1].z, acc[2][j]);
                    acc[3][j] = fmaf(wq.y, xq[1].w, acc[3][j]);
                    acc[0][j] = fmaf(wq.z, xq[2].x, acc[0][j]);
                    acc[1][j] = fmaf(wq.z, xq[2].y, acc[1][j]);
                    acc[2][j] = fmaf(wq.z, xq[2].z, acc[2][j]);
                    acc[3][j] = fmaf(wq.z, xq[2].w, acc[3][j]);
                    acc[0][j] = fmaf(wq.w, xq[3].x, acc[0][j]);
                    acc[1][j] = fmaf(wq.w, xq[3].y, acc[1][j]);
                    acc[2][j] = fmaf(wq.w, xq[3].z, acc[2][j]);
                    acc[3][j] = fmaf(wq.w, xq[3].w, acc[3][j]);
                }
            }
        }
    }
    __syncthreads();
    #pragma unroll
    for (int j = 0; j < 3; j++) {
        int c = ty + 16*j;
        if (c < 38) {
            float4 v; v.x = acc[0][j]; v.y = acc[1][j]; v.z = acc[2][j]; v.w = acc[3][j];
            *(float4*)&dbl[c*TTP + tx*4] = v;
        }
    }
    __syncthreads();

    for (int i = tid; i < DM*TT; i += 512) {
        int t = i % TT, d = i / TT;
        float s = 2.0f * dtb[d];
        #pragma unroll
        for (int r = 0; r < RT; r++) s = fmaf(dbl[r*TTP + t], dtw[d*RT + r], s);
        float dl = (s > 20.f) ? s : log1pf(__expf(s));
        g_dl[((size_t)b*DM + d)*L_ + l0 + t] = dl;
    }
    for (int i = tid; i < 2*NS*TT; i += 512) {
        int t = i % TT, q = i / TT;
        float v = dbl[(RT + q)*TTP + t];
        if (q < NS) g_Bs[((size_t)b*NS + q)*L_ + l0 + t] = v;
        else        g_Cs[((size_t)b*NS + (q-NS))*L_ + l0 + t] = v;
    }
}

/* ============ gate: z = silu(cat(xc,qp) @ gate_w^T + gate_b) ============ */
__global__ void __launch_bounds__(512)
gate_kernel(const float* __restrict__ gate_w, const float* __restrict__ gate_b)
{
    extern __shared__ float sm[];
    float* xs = sm;              // 96*TTP
    float* ws = xs + 96*TTP;     // 192*96
    int tid = threadIdx.x;
    int tok0 = blockIdx.x * TT;
    int b = tok0 / L_, l0 = tok0 % L_;
    int tx = tid & 31, ty = tid >> 5;

    float acc[4][12];
    #pragma unroll
    for (int m = 0; m < 4; m++)
        #pragma unroll
        for (int j = 0; j < 12; j++) acc[m][j] = 0.f;

    for (int kc = 0; kc < 4; kc++) {
        const float* src = (kc < 2) ? g_xc : g_qp;
        int k0 = (kc & 1) * 96;
        __syncthreads();
        for (int i = tid; i < 96*TT; i += 512) {
            int t = i % TT, k = i / TT;
            xs[k*TTP + t] = src[((size_t)b*DM + k0 + k)*L_ + l0 + t];
        }
        for (int i = tid; i < DM*96; i += 512) {
            int c = i / 96, kk = i % 96;
            ws[i] = gate_w[c*384 + kc*96 + kk];
        }
        __syncthreads();
        #pragma unroll 2
        for (int kk = 0; kk < 96; kk += 4) {
            float4 xq[4];
            #pragma unroll
            for (int q = 0; q < 4; q++)
                xq[q] = *(const float4*)&xs[(kk+q)*TTP + tx*4];
            #pragma unroll
            for (int j = 0; j < 12; j++) {
                float4 wq = *(const float4*)&ws[(ty + 16*j)*96 + kk];
                acc[0][j] = fmaf(wq.x, xq[0].x, acc[0][j]);
                acc[1][j] = fmaf(wq.x, xq[0].y, acc[1][j]);
                acc[2][j] = fmaf(wq.x, xq[0].z, acc[2][j]);
                acc[3][j] = fmaf(wq.x, xq[0].w, acc[3][j]);
                acc[0][j] = fmaf(wq.y, xq[1].x, acc[0][j]);
                acc[1][j] = fmaf(wq.y, xq[1].y, acc[1][j]);
                acc[2][j] = fmaf(wq.y, xq[1].z, acc[2][j]);
                acc[3][j] = fmaf(wq.y, xq[1].w, acc[3][j]);
                acc[0][j] = fmaf(wq.z, xq[2].x, acc[0][j]);
                acc[1][j] = fmaf(wq.z, xq[2].y, acc[1][j]);
                acc[2][j] = fmaf(wq.z, xq[2].z, acc[2][j]);
                acc[3][j] = fmaf(wq.z, xq[2].w, acc[3][j]);
                acc[0][j] = fmaf(wq.w, xq[3].x, acc[0][j]);
                acc[1][j] = fmaf(wq.w, xq[3].y, acc[1][j]);
                acc[2][j] = fmaf(wq.w, xq[3].z, acc[2][j]);
                acc[3][j] = fmaf(wq.w, xq[3].w, acc[3][j]);
            }
        }
    }
    float* dstb = g_z + ((size_t)b*DM)*L_ + l0;
    #pragma unroll
    for (int j = 0; j < 12; j++) {
        int c = ty + 16*j;
        float bv = gate_b[c];
        float4 v;
        v.x = siluf(acc[0][j] + bv); v.y = siluf(acc[1][j] + bv);
        v.z = siluf(acc[2][j] + bv); v.w = siluf(acc[3][j] + bv);
        *(float4*)&dstb[(size_t)c*L_ + tx*4] = v;
    }
}

/* ============ chunked selective scan ============ */
/* pass 1: per-chunk local scan from h=0 with smem staging */
__global__ void __launch_bounds__(256)
scan1(const float* __restrict__ A_log)
{
    __shared__ float dls[16*97], xcs[16*97], bs[16*97];
    int b = blockIdx.z, ch = blockIdx.y, dblk = blockIdx.x;
    int d0 = dblk*16;
    int tid = threadIdx.x;
    for (int i = tid; i < 16*G_; i += 256) {
        int r = i / G_, t = i % G_;
        dls[r*97+t] = g_dl[((size_t)b*DM + d0 + r)*L_ + ch*G_ + t];
        xcs[r*97+t] = g_xc[((size_t)b*DM + d0 + r)*L_ + ch*G_ + t];
        bs [r*97+t] = g_Bs[((size_t)b*NS + r)*L_ + ch*G_ + t];
    }
    __syncthreads();
    int n = tid & 15, dloc = tid >> 4;
    int d = d0 + dloc;
    float A = -__expf(A_log[d*NS + n]);
    float h = 0.f, S = 0.f;
    #pragma unroll 4
    for (int t = 0; t < G_; t++) {
        float dl = dls[dloc*97+t];
        float a = __expf(dl * A);
        S += dl;
        h = fmaf(a, h, dl * xcs[dloc*97+t] * bs[n*97+t]);
    }
    size_t o = (((size_t)(b*NCH + ch))*DM + d)*NS + n;
    g_P[o] = __expf(A * S); g_Hl[o] = h;
}

/* pass 2: combine chunk states sequentially */
__global__ void __launch_bounds__(256)
scan2()
{
    int idx = blockIdx.x * blockDim.x + threadIdx.x;
    if (idx >= B_*DM*NS) return;
    int b = idx / (DM*NS);
    int dn = idx % (DM*NS);
    float h = 0.f;
    for (int ch = 0; ch < NCH; ch++) {
        size_t o = ((size_t)(b*NCH + ch))*(DM*NS) + dn;
        g_Hi[o] = h;
        h = fmaf(g_P[o], h, g_Hl[o]);
    }
}

/* pass 3: re-scan with h0, reduce over n, D-skip, gate, coalesced y write */
__global__ void __launch_bounds__(256)
scan3(const float* __restrict__ A_log, const float* __restrict__ Dp)
{
    __shared__ float dls[16*97], xcs[16*97], bs[16*97], cs[16*97], zs[16*97], ys[16*97];
    int b = blockIdx.z, ch = blockIdx.y, dblk = blockIdx.x;
    int d0 = dblk*16;
    int tid = threadIdx.x;
    for (int i = tid; i < 16*G_; i += 256) {
        int r = i / G_, t = i % G_;
        size_t db = ((size_t)b*DM + d0 + r)*L_ + ch*G_ + t;
        size_t nb = ((size_t)b*NS + r)*L_ + ch*G_ + t;
        dls[r*97+t] = g_dl[db];
        xcs[r*97+t] = g_xc[db];
        zs [r*97+t] = g_z [db];
        bs [r*97+t] = g_Bs[nb];
        cs [r*97+t] = g_Cs[nb];
    }
    __syncthreads();
    int n = tid & 15, dloc = tid >> 4;
    int d = d0 + dloc;
    float A = -__expf(A_log[d*NS + n]);
    size_t o = (((size_t)(b*NCH + ch))*DM + d)*NS + n;
    float h = g_Hi[o];
    float Dd = Dp[d];
    for (int t = 0; t < G_; t++) {
        float dl = dls[dloc*97+t];
        float u  = xcs[dloc*97+t];
        float a = __expf(dl * A);
        h = fmaf(a, h, dl * u * bs[n*97+t]);
        float v = h * cs[n*97+t];
        v += __shfl_xor_sync(0xffffffffu, v, 1);
        v += __shfl_xor_sync(0xffffffffu, v, 2);
        v += __shfl_xor_sync(0xffffffffu, v, 4);
        v += __shfl_xor_sync(0xffffffffu, v, 8);
        if (n == 0)
            ys[dloc*97+t] = (v + u * Dd) * zs[dloc*97+t];
    }
    __syncthreads();
    for (int i = tid; i < 16*G_; i += 256) {
        int r = i / G_, t = i % G_;
        g_y[((size_t)b*DM + d0 + r)*L_ + ch*G_ + t] = ys[r*97+t];
    }
}

/* ============ out projection: out[b][c][l] ============ */
__global__ void __launch_bounds__(512)
gemm_out(const float* __restrict__ out_w, float* __restrict__ out)
{
    extern __shared__ float sm[];
    float* xs = sm;              // 96*TTP
    float* ws = xs + 96*TTP;     // 96*192
    int tid = threadIdx.x;
    int tok0 = blockIdx.x * TT;
    int b = tok0 / L_, l0 = tok0 % L_;
    for (int i = tid; i < CDIM*DM; i += 512) ws[i] = out_w[i];
    int tx = tid & 31, ty = tid >> 5;
    float acc[4][6];
    #pragma unroll
    for (int m = 0; m < 4; m++)
        #pragma unroll
        for (int j = 0; j < 6; j++) acc[m][j] = 0.f;

    for (int kc = 0; kc < 2; kc++) {
        __syncthreads();
        for (int i = tid; i < 96*TT; i += 512) {
            int t = i % TT, k = i / TT;
            xs[k*TTP + t] = g_y[((size_t)b*DM + kc*96 + k)*L_ + l0 + t];
        }
        __syncthreads();
        #pragma unroll 2
        for (int kk = 0; kk < 96; kk += 4) {
            float4 xq[4];
            #pragma unroll
            for (int q = 0; q < 4; q++)
                xq[q] = *(const float4*)&xs[(kk+q)*TTP + tx*4];
            #pragma unroll
            for (int j = 0; j < 6; j++) {
                float4 wq = *(const float4*)&ws[(ty + 16*j)*DM + kc*96 + kk];
                acc[0][j] = fmaf(wq.x, xq[0].x, acc[0][j]);
                acc[1][j] = fmaf(wq.x, xq[0].y, acc[1][j]);
                acc[2][j] = fmaf(wq.x, xq[0].z, acc[2][j]);
                acc[3][j] = fmaf(wq.x, xq[0].w, acc[3][j]);
                acc[0][j] = fmaf(wq.y, xq[1].x, acc[0][j]);
                acc[1][j] = fmaf(wq.y, xq[1].y, acc[1][j]);
                acc[2][j] = fmaf(wq.y, xq[1].z, acc[2][j]);
                acc[3][j] = fmaf(wq.y, xq[1].w, acc[3][j]);
                acc[0][j] = fmaf(wq.z, xq[2].x, acc[0][j]);
                acc[1][j] = fmaf(wq.z, xq[2].y, acc[1][j]);
                acc[2][j] = fmaf(wq.z, xq[2].z, acc[2][j]);
                acc[3][j] = fmaf(wq.z, xq[2].w, acc[3][j]);
                acc[0][j] = fmaf(wq.w, xq[3].x, acc[0][j]);
                acc[1][j] = fmaf(wq.w, xq[3].y, acc[1][j]);
                acc[2][j] = fmaf(wq.w, xq[3].z, acc[2][j]);
                acc[3][j] = fmaf(wq.w, xq[3].w, acc[3][j]);
            }
        }
    }
    float* ob = out + ((size_t)b*CDIM)*L_ + l0;
    #pragma unroll
    for (int j = 0; j < 6; j++) {
        int c = ty + 16*j;
        float4 v; v.x = acc[0][j]; v.y = acc[1][j]; v.z = acc[2][j]; v.w = acc[3][j];
        *(float4*)&ob[(size_t)c*L_ + tx*4] = v;
    }
}

/* ============ host launcher ============ */
extern "C" void kernel_launch(void* const* d_in, const int* in_sizes, int n_in,
                              void* d_out, int out_size)
{
    const float* x         = (const float*)d_in[0];
    const float* Kin       = (const float*)d_in[1];
    const float* Qin       = (const float*)d_in[2];
    const float* in_proj_w = (const float*)d_in[3];
    const float* conv_w    = (const float*)d_in[4];
    const float* conv_b    = (const float*)d_in[5];
    const float* k_ln_g    = (const float*)d_in[6];
    const float* k_ln_b    = (const float*)d_in[7];
    const float* k_w       = (const float*)d_in[8];
    const float* k_b       = (const float*)d_in[9];
    const float* q_ln_g    = (const float*)d_in[10];
    const float* q_ln_b    = (const float*)d_in[11];
    const float* q_w       = (const float*)d_in[12];
    const float* q_b       = (const float*)d_in[13];
    const float* dtbc_w    = (const float*)d_in[14];
    const float* dt_w      = (const float*)d_in[15];
    const float* dt_b      = (const float*)d_in[16];
    const float* gate_w    = (const float*)d_in[17];
    const float* gate_b    = (const float*)d_in[18];
    const float* A_log     = (const float*)d_in[19];
    const float* Dp        = (const float*)d_in[20];
    const float* out_w     = (const float*)d_in[21];
    float* out = (float*)d_out;

    const int SMEM_A = (96*TTP + 192*96 + 256) * 4;
    const int SMEM_G = (96*TTP + 192*96) * 4;
    const int SMEM_D = (96*TTP + 38*96 + 38*TTP + 192*6 + 192) * 4;
    const int SMEM_O = (96*TTP + 96*192) * 4;

    cudaFuncSetAttribute(gemm3_k96,   cudaFuncAttributeMaxDynamicSharedMemorySize, SMEM_A);
    cudaFuncSetAttribute(gate_kernel, cudaFuncAttributeMaxDynamicSharedMemorySize, SMEM_G);
    cudaFuncSetAttribute(dtbc_kernel, cudaFuncAttributeMaxDynamicSharedMemorySize, SMEM_D);
    cudaFuncSetAttribute(gemm_out,    cudaFuncAttributeMaxDynamicSharedMemorySize, SMEM_O);

    /* 1. fused in_proj + K-path + Q-path */
    gemm3_k96<<<dim3(NTILE,3), 512, SMEM_A>>>(x, Kin, Qin, in_proj_w,
        k_w, k_b, k_ln_g, k_ln_b, q_w, q_b, q_ln_g, q_ln_b);
    /* 2. depthwise conv + silu */
    conv_silu<<<(B_*DM*L_)/256, 256>>>(conv_w, conv_b);
    /* 3. dtbc -> delta, B, C */
    dtbc_kernel<<<NTILE, 512, SMEM_D>>>(dtbc_w, dt_w, dt_b);
    /* 4. gate -> silu(z) */
    gate_kernel<<<NTILE, 512, SMEM_G>>>(gate_w, gate_b);
    /* 5-7. chunked selective scan */
    scan1<<<dim3(DM/16, NCH, B_), 256>>>(A_log);
    scan2<<<(B_*DM*NS)/256, 256>>>();
    scan3<<<dim3(DM/16, NCH, B_), 256>>>(A_log, Dp);
    /* 8. output projection */
    gemm_out<<<NTILE, 512, SMEM_O>>>(out_w, out);
}